// round 1
// baseline (speedup 1.0000x reference)
#include <cuda_runtime.h>

// ---------------------------------------------------------------------------
// complexGRUCell: B=16384, I=256, H=256, fp32.
// Restructured as 2 real GEMMs + 2 elementwise passes:
//   GEMM1: C1[B,1536] = A[B,1024] @ G1^T   (A = [x_re|x_im|h_re|h_im])
//          groups: 0 r_re, 1 r_im, 2 z_re, 3 z_im, 4 ph_re, 5 ph_im
//   E1   : r = sigmoid(C1[g0,g1]+bias) ; RH = r (*) h  (complex)
//   GEMM2: C2[B,512] = RH[B,512] @ G2^T   (W_h hidden part)
//   E2   : z = sigmoid(C1[g2,g3]+bias); hh = tanh(C2 + C1[g4,g5]+bias);
//          out = gate-combine (complex)
// ---------------------------------------------------------------------------

#define B_ROWS 16384
#define HDIM   256
#define G1_N   1536
#define G1_K   1024
#define G2_N   512
#define G2_K   512

__device__ float g_G1[G1_N * G1_K];
__device__ float g_G2[G2_N * G2_K];
__device__ float g_bias[G1_N];
__device__ float g_C1[(size_t)B_ROWS * G1_N];
__device__ float g_RH[(size_t)B_ROWS * 512];
__device__ float g_C2[(size_t)B_ROWS * 512];

// ---- packed f32x2 helpers (sm_103a) ---------------------------------------
__device__ __forceinline__ unsigned long long pack2(float x) {
    unsigned long long r;
    asm("mov.b64 %0, {%1, %1};" : "=l"(r) : "r"(__float_as_uint(x)));
    return r;
}
__device__ __forceinline__ void fma2(unsigned long long& d,
                                     unsigned long long a,
                                     unsigned long long b) {
    asm("fma.rn.f32x2 %0, %1, %2, %0;" : "+l"(d) : "l"(a), "l"(b));
}
__device__ __forceinline__ float2 unpack2(unsigned long long v) {
    unsigned int lo, hi;
    asm("mov.b64 {%0, %1}, %2;" : "=r"(lo), "=r"(hi) : "l"(v));
    float2 r;
    r.x = __uint_as_float(lo);
    r.y = __uint_as_float(hi);
    return r;
}

// ---- weight preparation ----------------------------------------------------
__global__ void prep_g1(const float* __restrict__ wr_re, const float* __restrict__ wr_im,
                        const float* __restrict__ wz_re, const float* __restrict__ wz_im,
                        const float* __restrict__ wh_re, const float* __restrict__ wh_im,
                        const float* __restrict__ ur_re, const float* __restrict__ ur_im,
                        const float* __restrict__ uz_re, const float* __restrict__ uz_im,
                        const float* __restrict__ uh_re, const float* __restrict__ uh_im)
{
    int idx = blockIdx.x * blockDim.x + threadIdx.x;   // < 1536*1024
    int n = idx >> 10, k = idx & 1023;
    int g = n >> 8,  j = n & 255;
    int kg = k >> 8, kc = k & 255;

    const float *Wre, *Wim, *Ure, *Uim;
    if (g < 2)      { Wre = wr_re; Wim = wr_im; Ure = ur_re; Uim = ur_im; }
    else if (g < 4) { Wre = wz_re; Wim = wz_im; Ure = uz_re; Uim = uz_im; }
    else            { Wre = wh_re; Wim = wh_im; Ure = uh_re; Uim = uh_im; }
    bool isIm = (g & 1) != 0;
    bool isH  = (g >= 4);   // ph groups: W hidden part excluded (goes to GEMM2)

    int wj = j * 512;
    int uj = j * 256;
    float v;
    if (kg == 0) {          // x_re coefficient
        v = isIm ?  Wim[wj + kc] : Wre[wj + kc];
    } else if (kg == 1) {   // x_im coefficient
        v = isIm ?  Wre[wj + kc] : -Wim[wj + kc];
    } else if (kg == 2) {   // h_re coefficient
        if (isIm) v = (isH ? 0.f : Wim[wj + 256 + kc]) + Uim[uj + kc];
        else      v = (isH ? 0.f : Wre[wj + 256 + kc]) + Ure[uj + kc];
    } else {                // h_im coefficient
        if (isIm) v =  (isH ? 0.f : Wre[wj + 256 + kc]) + Ure[uj + kc];
        else      v = -((isH ? 0.f : Wim[wj + 256 + kc]) + Uim[uj + kc]);
    }
    g_G1[idx] = v;
}

__global__ void prep_g2(const float* __restrict__ wh_re,
                        const float* __restrict__ wh_im)
{
    int idx = blockIdx.x * blockDim.x + threadIdx.x;   // < 512*512
    int n = idx >> 9, k = idx & 511;
    int g = n >> 8,  j = n & 255;
    int kg = k >> 8, kc = k & 255;
    float wre = wh_re[j * 512 + 256 + kc];
    float wim = wh_im[j * 512 + 256 + kc];
    float v = (g == 0) ? ((kg == 0) ? wre : -wim)
                       : ((kg == 0) ? wim :  wre);
    g_G2[idx] = v;
}

__global__ void prep_bias(const float* __restrict__ wr_b_re, const float* __restrict__ wr_b_im,
                          const float* __restrict__ wz_b_re, const float* __restrict__ wz_b_im,
                          const float* __restrict__ wh_b_re, const float* __restrict__ wh_b_im)
{
    int idx = blockIdx.x * blockDim.x + threadIdx.x;   // < 1536
    int g = idx >> 8, j = idx & 255;
    const float *br, *bi;
    if (g < 2)      { br = wr_b_re; bi = wr_b_im; }
    else if (g < 4) { br = wz_b_re; bi = wz_b_im; }
    else            { br = wh_b_re; bi = wh_b_im; }
    g_bias[idx] = (g & 1) ? (br[j] + bi[j]) : (br[j] - bi[j]);
}

// ---- SGEMM: C[M,N] = A[M,K] @ W[N,K]^T  (A is 4 column-groups of 256) ------
#define BM 128
#define BN 128
#define BK 16

__global__ __launch_bounds__(256, 2)
void sgemm_kernel(int mode,
                  const float* a0, const float* a1,
                  const float* a2p, const float* a3,
                  int aStride, int N, int K)
{
    __shared__ float As[BK][BM];
    __shared__ float Bs[BK][BN];

    const float* W;
    float* C;
    const float* asrc[4];
    if (mode == 0) {
        W = g_G1; C = g_C1;
        asrc[0] = a0; asrc[1] = a1; asrc[2] = a2p; asrc[3] = a3;
    } else {
        W = g_G2; C = g_C2;
        asrc[0] = g_RH; asrc[1] = g_RH + 256; asrc[2] = g_RH; asrc[3] = g_RH;
    }

    const int tid = threadIdx.x;
    const int tx = tid & 15;       // n-dir microtile
    const int ty = tid >> 4;       // m-dir microtile
    const int mBlk = blockIdx.y * BM;
    const int nBlk = blockIdx.x * BN;

    const int lrow = tid >> 2;           // 0..63
    const int lk   = (tid & 3) << 2;     // {0,4,8,12}

    unsigned long long acc[4][8];
#pragma unroll
    for (int i = 0; i < 4; ++i)
#pragma unroll
        for (int j = 0; j < 8; ++j) acc[i][j] = 0ull;

    float4 aR0, aR1, bR0, bR1;
    {
        const float* s = asrc[0];
        aR0 = *(const float4*)(s + (size_t)(mBlk + lrow)      * aStride + lk);
        aR1 = *(const float4*)(s + (size_t)(mBlk + lrow + 64) * aStride + lk);
        bR0 = *(const float4*)(W + (size_t)(nBlk + lrow)      * K + lk);
        bR1 = *(const float4*)(W + (size_t)(nBlk + lrow + 64) * K + lk);
    }

    for (int k0 = 0; k0 < K; k0 += BK) {
        __syncthreads();
        As[lk + 0][lrow]      = aR0.x; As[lk + 1][lrow]      = aR0.y;
        As[lk + 2][lrow]      = aR0.z; As[lk + 3][lrow]      = aR0.w;
        As[lk + 0][lrow + 64] = aR1.x; As[lk + 1][lrow + 64] = aR1.y;
        As[lk + 2][lrow + 64] = aR1.z; As[lk + 3][lrow + 64] = aR1.w;
        Bs[lk + 0][lrow]      = bR0.x; Bs[lk + 1][lrow]      = bR0.y;
        Bs[lk + 2][lrow]      = bR0.z; Bs[lk + 3][lrow]      = bR0.w;
        Bs[lk + 0][lrow + 64] = bR1.x; Bs[lk + 1][lrow + 64] = bR1.y;
        Bs[lk + 2][lrow + 64] = bR1.z; Bs[lk + 3][lrow + 64] = bR1.w;
        __syncthreads();

        int kn = k0 + BK;
        if (kn < K) {   // prefetch next tile (hides LDG under FMA)
            const float* s = asrc[kn >> 8];
            int col = (kn & 255) + lk;
            aR0 = *(const float4*)(s + (size_t)(mBlk + lrow)      * aStride + col);
            aR1 = *(const float4*)(s + (size_t)(mBlk + lrow + 64) * aStride + col);
            bR0 = *(const float4*)(W + (size_t)(nBlk + lrow)      * K + kn + lk);
            bR1 = *(const float4*)(W + (size_t)(nBlk + lrow + 64) * K + kn + lk);
        }

#pragma unroll
        for (int kk = 0; kk < BK; ++kk) {
            unsigned long long av[4];
#pragma unroll
            for (int i = 0; i < 4; ++i)
                av[i] = *(const unsigned long long*)&As[kk][ty * 8 + 2 * i];
            float4 b0 = *(const float4*)&Bs[kk][tx * 8];
            float4 b1 = *(const float4*)&Bs[kk][tx * 8 + 4];
            float bv[8] = {b0.x, b0.y, b0.z, b0.w, b1.x, b1.y, b1.z, b1.w};
#pragma unroll
            for (int j = 0; j < 8; ++j) {
                unsigned long long bb = pack2(bv[j]);
                fma2(acc[0][j], av[0], bb);
                fma2(acc[1][j], av[1], bb);
                fma2(acc[2][j], av[2], bb);
                fma2(acc[3][j], av[3], bb);
            }
        }
    }

    // epilogue: unpack pairs, store float4
#pragma unroll
    for (int mp = 0; mp < 4; ++mp) {
        float lo[8], hi[8];
#pragma unroll
        for (int j = 0; j < 8; ++j) {
            float2 v = unpack2(acc[mp][j]);
            lo[j] = v.x; hi[j] = v.y;
        }
        size_t base0 = (size_t)(mBlk + ty * 8 + 2 * mp) * N + nBlk + tx * 8;
        size_t base1 = base0 + N;
        *(float4*)&C[base0]     = make_float4(lo[0], lo[1], lo[2], lo[3]);
        *(float4*)&C[base0 + 4] = make_float4(lo[4], lo[5], lo[6], lo[7]);
        *(float4*)&C[base1]     = make_float4(hi[0], hi[1], hi[2], hi[3]);
        *(float4*)&C[base1 + 4] = make_float4(hi[4], hi[5], hi[6], hi[7]);
    }
}

// ---- elementwise -----------------------------------------------------------
__device__ __forceinline__ float sigmoidf_(float x) {
    return 1.0f / (1.0f + __expf(-x));
}

__global__ void e1_kernel(const float* __restrict__ h_re,
                          const float* __restrict__ h_im)
{
    int idx = blockIdx.x * blockDim.x + threadIdx.x;   // < B*H
    int b = idx >> 8, j = idx & 255;
    size_t row = (size_t)b * G1_N;
    float rr = sigmoidf_(g_C1[row + j]       + g_bias[j]);
    float ri = sigmoidf_(g_C1[row + 256 + j] + g_bias[256 + j]);
    float hr = h_re[idx], hi = h_im[idx];
    size_t r2 = (size_t)b * 512;
    g_RH[r2 + j]       = rr * hr - ri * hi;
    g_RH[r2 + 256 + j] = rr * hi + ri * hr;
}

__global__ void e2_kernel(const float* __restrict__ h_re,
                          const float* __restrict__ h_im,
                          float* __restrict__ out)
{
    int idx = blockIdx.x * blockDim.x + threadIdx.x;   // < B*H
    int b = idx >> 8, j = idx & 255;
    size_t r1 = (size_t)b * G1_N;
    size_t r2 = (size_t)b * 512;
    float zr = sigmoidf_(g_C1[r1 + 512 + j] + g_bias[512 + j]);
    float zi = sigmoidf_(g_C1[r1 + 768 + j] + g_bias[768 + j]);
    float er = g_C2[r2 + j]       + g_C1[r1 + 1024 + j] + g_bias[1024 + j];
    float ei = g_C2[r2 + 256 + j] + g_C1[r1 + 1280 + j] + g_bias[1280 + j];
    float hhr = tanhf(er);
    float hhi = tanhf(ei);
    float hr = h_re[idx], hi = h_im[idx];
    out[idx] = (1.0f - zr) * hr + zi * hi + zr * hhr - zi * hhi;
    out[(size_t)B_ROWS * HDIM + idx] =
        (1.0f - zr) * hi - zi * hr + zr * hhi + zi * hhr;
}

// ---- launch ----------------------------------------------------------------
extern "C" void kernel_launch(void* const* d_in, const int* in_sizes, int n_in,
                              void* d_out, int out_size)
{
    const float* x_re    = (const float*)d_in[0];
    const float* x_im    = (const float*)d_in[1];
    const float* h_re    = (const float*)d_in[2];
    const float* h_im    = (const float*)d_in[3];
    const float* wr_w_re = (const float*)d_in[4];
    const float* wr_w_im = (const float*)d_in[5];
    const float* wr_b_re = (const float*)d_in[6];
    const float* wr_b_im = (const float*)d_in[7];
    const float* wz_w_re = (const float*)d_in[8];
    const float* wz_w_im = (const float*)d_in[9];
    const float* wz_b_re = (const float*)d_in[10];
    const float* wz_b_im = (const float*)d_in[11];
    const float* wh_w_re = (const float*)d_in[12];
    const float* wh_w_im = (const float*)d_in[13];
    const float* wh_b_re = (const float*)d_in[14];
    const float* wh_b_im = (const float*)d_in[15];
    const float* ur_w_re = (const float*)d_in[16];
    const float* ur_w_im = (const float*)d_in[17];
    const float* uz_w_re = (const float*)d_in[18];
    const float* uz_w_im = (const float*)d_in[19];
    const float* uh_w_re = (const float*)d_in[20];
    const float* uh_w_im = (const float*)d_in[21];

    prep_g1<<<(G1_N * G1_K) / 256, 256>>>(wr_w_re, wr_w_im, wz_w_re, wz_w_im,
                                          wh_w_re, wh_w_im, ur_w_re, ur_w_im,
                                          uz_w_re, uz_w_im, uh_w_re, uh_w_im);
    prep_g2<<<(G2_N * G2_K) / 256, 256>>>(wh_w_re, wh_w_im);
    prep_bias<<<G1_N / 256, 256>>>(wr_b_re, wr_b_im, wz_b_re, wz_b_im,
                                   wh_b_re, wh_b_im);

    dim3 blk(256);
    dim3 grid1(G1_N / BN, B_ROWS / BM);
    sgemm_kernel<<<grid1, blk>>>(0, x_re, x_im, h_re, h_im, HDIM, G1_N, G1_K);

    e1_kernel<<<(B_ROWS * HDIM) / 256, 256>>>(h_re, h_im);

    dim3 grid2(G2_N / BN, B_ROWS / BM);
    sgemm_kernel<<<grid2, blk>>>(1, nullptr, nullptr, nullptr, nullptr,
                                 512, G2_N, G2_K);

    e2_kernel<<<(B_ROWS * HDIM) / 256, 256>>>(h_re, h_im, (float*)d_out);
}

// round 2
// speedup vs baseline: 2.7153x; 2.7153x over previous
#include <cuda_runtime.h>

// ---------------------------------------------------------------------------
// complexGRUCell: B=16384, I=256, H=256, fp32 in/out, TF32 tensor-core GEMMs.
//   GEMM1: C1[B,1536] = A[B,1024] @ G1^T   (A = [x_re|x_im|h_re|h_im])
//   E1   : r = sigmoid(C1[g0,g1]+bias) ; RH = r (*) h  (complex)
//   GEMM2: C2[B,512] = RH[B,512] @ G2^T
//   E2   : z, tanh, gate-combine -> out
// GEMMs use mma.sync.m16n8k8.row.col.tf32 (weights rna-rounded to tf32,
// activations truncated).
// ---------------------------------------------------------------------------

#define B_ROWS 16384
#define HDIM   256
#define G1_N   1536
#define G1_K   1024
#define G2_N   512
#define G2_K   512

__device__ float g_G1[G1_N * G1_K];
__device__ float g_G2[G2_N * G2_K];
__device__ float g_bias[G1_N];
__device__ float g_C1[(size_t)B_ROWS * G1_N];
__device__ float g_RH[(size_t)B_ROWS * 512];
__device__ float g_C2[(size_t)B_ROWS * 512];

__device__ __forceinline__ float to_tf32(float x) {
    unsigned u;
    asm("cvt.rna.tf32.f32 %0, %1;" : "=r"(u) : "f"(x));
    return __uint_as_float(u);
}

__device__ __forceinline__ void mma_tf32(float* c, const unsigned* a,
                                         const unsigned* b) {
    asm volatile(
        "mma.sync.aligned.m16n8k8.row.col.f32.tf32.tf32.f32 "
        "{%0,%1,%2,%3}, {%4,%5,%6,%7}, {%8,%9}, {%0,%1,%2,%3};"
        : "+f"(c[0]), "+f"(c[1]), "+f"(c[2]), "+f"(c[3])
        : "r"(a[0]), "r"(a[1]), "r"(a[2]), "r"(a[3]), "r"(b[0]), "r"(b[1]));
}

// ---- weight preparation (pre-rounded to tf32) -------------------------------
__global__ void prep_g1(const float* __restrict__ wr_re, const float* __restrict__ wr_im,
                        const float* __restrict__ wz_re, const float* __restrict__ wz_im,
                        const float* __restrict__ wh_re, const float* __restrict__ wh_im,
                        const float* __restrict__ ur_re, const float* __restrict__ ur_im,
                        const float* __restrict__ uz_re, const float* __restrict__ uz_im,
                        const float* __restrict__ uh_re, const float* __restrict__ uh_im)
{
    int idx = blockIdx.x * blockDim.x + threadIdx.x;   // < 1536*1024
    int n = idx >> 10, k = idx & 1023;
    int g = n >> 8,  j = n & 255;
    int kg = k >> 8, kc = k & 255;

    const float *Wre, *Wim, *Ure, *Uim;
    if (g < 2)      { Wre = wr_re; Wim = wr_im; Ure = ur_re; Uim = ur_im; }
    else if (g < 4) { Wre = wz_re; Wim = wz_im; Ure = uz_re; Uim = uz_im; }
    else            { Wre = wh_re; Wim = wh_im; Ure = uh_re; Uim = uh_im; }
    bool isIm = (g & 1) != 0;
    bool isH  = (g >= 4);

    int wj = j * 512;
    int uj = j * 256;
    float v;
    if (kg == 0) {
        v = isIm ?  Wim[wj + kc] : Wre[wj + kc];
    } else if (kg == 1) {
        v = isIm ?  Wre[wj + kc] : -Wim[wj + kc];
    } else if (kg == 2) {
        if (isIm) v = (isH ? 0.f : Wim[wj + 256 + kc]) + Uim[uj + kc];
        else      v = (isH ? 0.f : Wre[wj + 256 + kc]) + Ure[uj + kc];
    } else {
        if (isIm) v =  (isH ? 0.f : Wre[wj + 256 + kc]) + Ure[uj + kc];
        else      v = -((isH ? 0.f : Wim[wj + 256 + kc]) + Uim[uj + kc]);
    }
    g_G1[idx] = to_tf32(v);
}

__global__ void prep_g2(const float* __restrict__ wh_re,
                        const float* __restrict__ wh_im)
{
    int idx = blockIdx.x * blockDim.x + threadIdx.x;   // < 512*512
    int n = idx >> 9, k = idx & 511;
    int g = n >> 8,  j = n & 255;
    int kg = k >> 8, kc = k & 255;
    float wre = wh_re[j * 512 + 256 + kc];
    float wim = wh_im[j * 512 + 256 + kc];
    float v = (g == 0) ? ((kg == 0) ? wre : -wim)
                       : ((kg == 0) ? wim :  wre);
    g_G2[idx] = to_tf32(v);
}

__global__ void prep_bias(const float* __restrict__ wr_b_re, const float* __restrict__ wr_b_im,
                          const float* __restrict__ wz_b_re, const float* __restrict__ wz_b_im,
                          const float* __restrict__ wh_b_re, const float* __restrict__ wh_b_im)
{
    int idx = blockIdx.x * blockDim.x + threadIdx.x;   // < 1536
    int g = idx >> 8, j = idx & 255;
    const float *br, *bi;
    if (g < 2)      { br = wr_b_re; bi = wr_b_im; }
    else if (g < 4) { br = wz_b_re; bi = wz_b_im; }
    else            { br = wh_b_re; bi = wh_b_im; }
    g_bias[idx] = (g & 1) ? (br[j] + bi[j]) : (br[j] - bi[j]);
}

// ---- TF32 tensor-core GEMM: C[M,N] = A[M,K] @ W[N,K]^T ---------------------
// CTA tile 128x128, BK=32, 256 threads = 8 warps (2 m-warps x 4 n-warps),
// warp tile 64x32, mma.m16n8k8.
#define BM 128
#define BN 128
#define BK 32
#define LDT 36   // smem row stride (BK + 4 pad)

__global__ __launch_bounds__(256, 1)
void mma_gemm(int mode,
              const float* a0, const float* a1,
              const float* a2p, const float* a3,
              int aStride, int N, int K)
{
    __shared__ float As[BM * LDT];   // [m][k]
    __shared__ float Bs[BN * LDT];   // [n][k]

    const float* W;
    float* C;
    const float* asrc[4];
    if (mode == 0) {
        W = g_G1; C = g_C1;
        asrc[0] = a0; asrc[1] = a1; asrc[2] = a2p; asrc[3] = a3;
    } else {
        W = g_G2; C = g_C2;
        asrc[0] = g_RH; asrc[1] = g_RH + 256; asrc[2] = g_RH; asrc[3] = g_RH;
    }

    const int tid  = threadIdx.x;
    const int lane = tid & 31;
    const int wid  = tid >> 5;
    const int wm   = wid & 1;        // m-warp (0..1)
    const int wn   = wid >> 1;       // n-warp (0..3)
    const int grp  = lane >> 2;      // 0..7
    const int qid  = lane & 3;       // 0..3

    const int mBlk = blockIdx.y * BM;
    const int nBlk = blockIdx.x * BN;

    // gmem load mapping: each thread loads 4 float4s per tile
    const int lrow = tid >> 3;        // 0..31 (+32 per pass)
    const int lcol = (tid & 7) << 2;  // 0,4,..,28

    float c[4][4][4];
#pragma unroll
    for (int i = 0; i < 4; ++i)
#pragma unroll
        for (int j = 0; j < 4; ++j)
#pragma unroll
            for (int r = 0; r < 4; ++r) c[i][j][r] = 0.f;

    float4 aR[4], bR[4];
    {
        const float* s = asrc[0];
#pragma unroll
        for (int p = 0; p < 4; ++p) {
            aR[p] = *(const float4*)(s + (size_t)(mBlk + lrow + 32 * p) * aStride + lcol);
            bR[p] = *(const float4*)(W + (size_t)(nBlk + lrow + 32 * p) * K + lcol);
        }
    }

    for (int k0 = 0; k0 < K; k0 += BK) {
        __syncthreads();
#pragma unroll
        for (int p = 0; p < 4; ++p) {
            *(float4*)&As[(lrow + 32 * p) * LDT + lcol] = aR[p];
            *(float4*)&Bs[(lrow + 32 * p) * LDT + lcol] = bR[p];
        }
        __syncthreads();

        int kn = k0 + BK;
        if (kn < K) {
            const float* s = asrc[kn >> 8];
            int col = (kn & 255) + lcol;
#pragma unroll
            for (int p = 0; p < 4; ++p) {
                aR[p] = *(const float4*)(s + (size_t)(mBlk + lrow + 32 * p) * aStride + col);
                bR[p] = *(const float4*)(W + (size_t)(nBlk + lrow + 32 * p) * K + kn + lcol);
            }
        }

#pragma unroll
        for (int kk = 0; kk < 4; ++kk) {
            const int kb = kk * 8;
            unsigned afr[4][4], bfr[4][2];
#pragma unroll
            for (int mt = 0; mt < 4; ++mt) {
                int m0 = (wm * 64 + mt * 16 + grp) * LDT + kb + qid;
                afr[mt][0] = __float_as_uint(As[m0]);
                afr[mt][1] = __float_as_uint(As[m0 + 8 * LDT]);
                afr[mt][2] = __float_as_uint(As[m0 + 4]);
                afr[mt][3] = __float_as_uint(As[m0 + 8 * LDT + 4]);
            }
#pragma unroll
            for (int nt = 0; nt < 4; ++nt) {
                int n0 = (wn * 32 + nt * 8 + grp) * LDT + kb + qid;
                bfr[nt][0] = __float_as_uint(Bs[n0]);
                bfr[nt][1] = __float_as_uint(Bs[n0 + 4]);
            }
#pragma unroll
            for (int mt = 0; mt < 4; ++mt)
#pragma unroll
                for (int nt = 0; nt < 4; ++nt)
                    mma_tf32(c[mt][nt], afr[mt], bfr[nt]);
        }
    }

    // epilogue
#pragma unroll
    for (int mt = 0; mt < 4; ++mt) {
#pragma unroll
        for (int nt = 0; nt < 4; ++nt) {
            int row = mBlk + wm * 64 + mt * 16 + grp;
            int col = nBlk + wn * 32 + nt * 8 + qid * 2;
            float2 v0 = make_float2(c[mt][nt][0], c[mt][nt][1]);
            float2 v1 = make_float2(c[mt][nt][2], c[mt][nt][3]);
            *(float2*)&C[(size_t)row * N + col]       = v0;
            *(float2*)&C[(size_t)(row + 8) * N + col] = v1;
        }
    }
}

// ---- elementwise -----------------------------------------------------------
__device__ __forceinline__ float sigmoidf_(float x) {
    return 1.0f / (1.0f + __expf(-x));
}

__global__ void e1_kernel(const float* __restrict__ h_re,
                          const float* __restrict__ h_im)
{
    int idx = blockIdx.x * blockDim.x + threadIdx.x;   // < B*H
    int b = idx >> 8, j = idx & 255;
    size_t row = (size_t)b * G1_N;
    float rr = sigmoidf_(g_C1[row + j]       + g_bias[j]);
    float ri = sigmoidf_(g_C1[row + 256 + j] + g_bias[256 + j]);
    float hr = h_re[idx], hi = h_im[idx];
    size_t r2 = (size_t)b * 512;
    g_RH[r2 + j]       = to_tf32(rr * hr - ri * hi);
    g_RH[r2 + 256 + j] = to_tf32(rr * hi + ri * hr);
}

__global__ void e2_kernel(const float* __restrict__ h_re,
                          const float* __restrict__ h_im,
                          float* __restrict__ out)
{
    int idx = blockIdx.x * blockDim.x + threadIdx.x;   // < B*H
    int b = idx >> 8, j = idx & 255;
    size_t r1 = (size_t)b * G1_N;
    size_t r2 = (size_t)b * 512;
    float zr = sigmoidf_(g_C1[r1 + 512 + j] + g_bias[512 + j]);
    float zi = sigmoidf_(g_C1[r1 + 768 + j] + g_bias[768 + j]);
    float er = g_C2[r2 + j]       + g_C1[r1 + 1024 + j] + g_bias[1024 + j];
    float ei = g_C2[r2 + 256 + j] + g_C1[r1 + 1280 + j] + g_bias[1280 + j];
    float hhr = tanhf(er);
    float hhi = tanhf(ei);
    float hr = h_re[idx], hi = h_im[idx];
    out[idx] = (1.0f - zr) * hr + zi * hi + zr * hhr - zi * hhi;
    out[(size_t)B_ROWS * HDIM + idx] =
        (1.0f - zr) * hi - zi * hr + zr * hhi + zi * hhr;
}

// ---- launch ----------------------------------------------------------------
extern "C" void kernel_launch(void* const* d_in, const int* in_sizes, int n_in,
                              void* d_out, int out_size)
{
    const float* x_re    = (const float*)d_in[0];
    const float* x_im    = (const float*)d_in[1];
    const float* h_re    = (const float*)d_in[2];
    const float* h_im    = (const float*)d_in[3];
    const float* wr_w_re = (const float*)d_in[4];
    const float* wr_w_im = (const float*)d_in[5];
    const float* wr_b_re = (const float*)d_in[6];
    const float* wr_b_im = (const float*)d_in[7];
    const float* wz_w_re = (const float*)d_in[8];
    const float* wz_w_im = (const float*)d_in[9];
    const float* wz_b_re = (const float*)d_in[10];
    const float* wz_b_im = (const float*)d_in[11];
    const float* wh_w_re = (const float*)d_in[12];
    const float* wh_w_im = (const float*)d_in[13];
    const float* wh_b_re = (const float*)d_in[14];
    const float* wh_b_im = (const float*)d_in[15];
    const float* ur_w_re = (const float*)d_in[16];
    const float* ur_w_im = (const float*)d_in[17];
    const float* uz_w_re = (const float*)d_in[18];
    const float* uz_w_im = (const float*)d_in[19];
    const float* uh_w_re = (const float*)d_in[20];
    const float* uh_w_im = (const float*)d_in[21];

    prep_g1<<<(G1_N * G1_K) / 256, 256>>>(wr_w_re, wr_w_im, wz_w_re, wz_w_im,
                                          wh_w_re, wh_w_im, ur_w_re, ur_w_im,
                                          uz_w_re, uz_w_im, uh_w_re, uh_w_im);
    prep_g2<<<(G2_N * G2_K) / 256, 256>>>(wh_w_re, wh_w_im);
    prep_bias<<<G1_N / 256, 256>>>(wr_b_re, wr_b_im, wz_b_re, wz_b_im,
                                   wh_b_re, wh_b_im);

    dim3 blk(256);
    dim3 grid1(G1_N / BN, B_ROWS / BM);
    mma_gemm<<<grid1, blk>>>(0, x_re, x_im, h_re, h_im, HDIM, G1_N, G1_K);

    e1_kernel<<<(B_ROWS * HDIM) / 256, 256>>>(h_re, h_im);

    dim3 grid2(G2_N / BN, B_ROWS / BM);
    mma_gemm<<<grid2, blk>>>(1, nullptr, nullptr, nullptr, nullptr,
                             512, G2_N, G2_K);

    e2_kernel<<<(B_ROWS * HDIM) / 256, 256>>>(h_re, h_im, (float*)d_out);
}

// round 6
// speedup vs baseline: 4.1340x; 1.5224x over previous
#include <cuda_runtime.h>
#include <cuda_fp16.h>
#include <cstdint>

// ---------------------------------------------------------------------------
// complexGRUCell: B=16384, I=256, H=256, fp32 in/out.
// fp16 tensor-core GEMMs (mma.m16n8k16.f32.f16.f16.f32).
// NOTE: all __device__ globals are resolved INSIDE device code via mode flags
// (passing a __device__ symbol as a host-side kernel arg silently reads the
// host shadow on GB300/ATS — root cause of R4/R5 failures).
// ---------------------------------------------------------------------------

#define B_ROWS 16384
#define HDIM   256
#define G1_N   1536
#define G1_K   1024
#define G2_N   512
#define G2_K   512

__device__ __half g_G1h[G1_N * G1_K];
__device__ __half g_G2h[G2_N * G2_K];
__device__ __half g_Ah[(size_t)B_ROWS * G1_K];
__device__ __half g_RHh[(size_t)B_ROWS * 512];
__device__ float  g_bias[G1_N];
__device__ float  g_C1[(size_t)B_ROWS * G1_N];
__device__ float  g_C2[(size_t)B_ROWS * 512];

__device__ __forceinline__ void mma_f16(float* c, const uint32_t* a,
                                        const uint32_t* b) {
    asm volatile(
        "mma.sync.aligned.m16n8k16.row.col.f32.f16.f16.f32 "
        "{%0,%1,%2,%3}, {%4,%5,%6,%7}, {%8,%9}, {%0,%1,%2,%3};"
        : "+f"(c[0]), "+f"(c[1]), "+f"(c[2]), "+f"(c[3])
        : "r"(a[0]), "r"(a[1]), "r"(a[2]), "r"(a[3]), "r"(b[0]), "r"(b[1]));
}

// ---- weight / activation preparation ----------------------------------------
__global__ void prep_g1(const float* __restrict__ wr_re, const float* __restrict__ wr_im,
                        const float* __restrict__ wz_re, const float* __restrict__ wz_im,
                        const float* __restrict__ wh_re, const float* __restrict__ wh_im,
                        const float* __restrict__ ur_re, const float* __restrict__ ur_im,
                        const float* __restrict__ uz_re, const float* __restrict__ uz_im,
                        const float* __restrict__ uh_re, const float* __restrict__ uh_im)
{
    int idx = blockIdx.x * blockDim.x + threadIdx.x;
    int n = idx >> 10, k = idx & 1023;
    int g = n >> 8,  j = n & 255;
    int kg = k >> 8, kc = k & 255;

    const float *Wre, *Wim, *Ure, *Uim;
    if (g < 2)      { Wre = wr_re; Wim = wr_im; Ure = ur_re; Uim = ur_im; }
    else if (g < 4) { Wre = wz_re; Wim = wz_im; Ure = uz_re; Uim = uz_im; }
    else            { Wre = wh_re; Wim = wh_im; Ure = uh_re; Uim = uh_im; }
    bool isIm = (g & 1) != 0;
    bool isH  = (g >= 4);

    int wj = j * 512;
    int uj = j * 256;
    float v;
    if (kg == 0) {
        v = isIm ?  Wim[wj + kc] : Wre[wj + kc];
    } else if (kg == 1) {
        v = isIm ?  Wre[wj + kc] : -Wim[wj + kc];
    } else if (kg == 2) {
        if (isIm) v = (isH ? 0.f : Wim[wj + 256 + kc]) + Uim[uj + kc];
        else      v = (isH ? 0.f : Wre[wj + 256 + kc]) + Ure[uj + kc];
    } else {
        if (isIm) v =  (isH ? 0.f : Wre[wj + 256 + kc]) + Ure[uj + kc];
        else      v = -((isH ? 0.f : Wim[wj + 256 + kc]) + Uim[uj + kc]);
    }
    g_G1h[idx] = __float2half(v);
}

__global__ void prep_g2(const float* __restrict__ wh_re,
                        const float* __restrict__ wh_im)
{
    int idx = blockIdx.x * blockDim.x + threadIdx.x;
    int n = idx >> 9, k = idx & 511;
    int g = n >> 8,  j = n & 255;
    int kg = k >> 8, kc = k & 255;
    float wre = wh_re[j * 512 + 256 + kc];
    float wim = wh_im[j * 512 + 256 + kc];
    float v = (g == 0) ? ((kg == 0) ? wre : -wim)
                       : ((kg == 0) ? wim :  wre);
    g_G2h[idx] = __float2half(v);
}

__global__ void prep_bias(const float* __restrict__ wr_b_re, const float* __restrict__ wr_b_im,
                          const float* __restrict__ wz_b_re, const float* __restrict__ wz_b_im,
                          const float* __restrict__ wh_b_re, const float* __restrict__ wh_b_im)
{
    int idx = blockIdx.x * blockDim.x + threadIdx.x;
    int g = idx >> 8, j = idx & 255;
    const float *br, *bi;
    if (g < 2)      { br = wr_b_re; bi = wr_b_im; }
    else if (g < 4) { br = wz_b_re; bi = wz_b_im; }
    else            { br = wh_b_re; bi = wh_b_im; }
    g_bias[idx] = (g & 1) ? (br[j] + bi[j]) : (br[j] - bi[j]);
}

__global__ void convA(const float* __restrict__ x_re, const float* __restrict__ x_im,
                      const float* __restrict__ h_re, const float* __restrict__ h_im)
{
    int idx = blockIdx.x * blockDim.x + threadIdx.x;   // < B*256
    int b = idx >> 8;
    int k = (idx & 255) << 2;
    int plane = k >> 8, kc = k & 255;
    const float* src = (plane == 0) ? x_re : (plane == 1) ? x_im
                     : (plane == 2) ? h_re : h_im;
    float4 v = *(const float4*)(src + (size_t)b * 256 + kc);
    __half2* dst = (__half2*)(g_Ah + (size_t)b * 1024 + k);
    dst[0] = __floats2half2_rn(v.x, v.y);
    dst[1] = __floats2half2_rn(v.z, v.w);
}

// ---- fp16 tensor-core GEMM: C[M,N] = A[M,K] @ W[N,K]^T ----------------------
// CTA 128x128, BK=32 halves, 8 warps (2m x 4n), warp tile 64x32, m16n8k16.
// mode 0: A=g_Ah (lda 1024), W=g_G1h, C=g_C1 (N=1536, K=1024)
// mode 1: A=g_RHh (lda 512), W=g_G2h, C=g_C2 (N=512,  K=512)
#define BM 128
#define BN 128
#define BKH 32
#define LDH 40    // halves per smem row (32 + 8 pad): bank-conflict-free

__global__ void __launch_bounds__(256, 2)
hgemm(int mode)
{
    __shared__ __half As[BM][LDH];
    __shared__ __half Bs[BN][LDH];

    const __half* A;
    const __half* W;
    float* C;
    int lda, N, K;
    if (mode == 0) {
        A = g_Ah;  W = g_G1h; C = g_C1; lda = G1_K; N = G1_N; K = G1_K;
    } else {
        A = g_RHh; W = g_G2h; C = g_C2; lda = G2_K; N = G2_N; K = G2_K;
    }

    const int tid  = threadIdx.x;
    const int lane = tid & 31;
    const int wid  = tid >> 5;
    const int wm   = wid & 1;        // m-warp (0..1)
    const int wn   = wid >> 1;       // n-warp (0..3)
    const int grp  = lane >> 2;      // 0..7
    const int qid  = lane & 3;       // 0..3
    const int mBlk = blockIdx.y * BM;
    const int nBlk = blockIdx.x * BN;

    // loader mapping: 256 threads; rows lrow & lrow+64, 16B segment each
    const int lrow = tid >> 2;       // 0..63
    const int seg  = tid & 3;        // 0..3 (16B = 8 halves)
    const __half* gA1 = A + (size_t)(mBlk + lrow)      * lda + seg * 8;
    const __half* gA2 = A + (size_t)(mBlk + lrow + 64) * lda + seg * 8;
    const __half* gB1 = W + (size_t)(nBlk + lrow)      * K   + seg * 8;
    const __half* gB2 = W + (size_t)(nBlk + lrow + 64) * K   + seg * 8;

    float c[4][4][4];
#pragma unroll
    for (int i = 0; i < 4; ++i)
#pragma unroll
        for (int j = 0; j < 4; ++j)
#pragma unroll
            for (int r = 0; r < 4; ++r) c[i][j][r] = 0.f;

    uint4 aR0, aR1, bR0, bR1;
    aR0 = *(const uint4*)gA1;
    aR1 = *(const uint4*)gA2;
    bR0 = *(const uint4*)gB1;
    bR1 = *(const uint4*)gB2;

    for (int k0 = 0; k0 < K; k0 += BKH) {
        __syncthreads();
        *(uint4*)&As[lrow][seg * 8]      = aR0;
        *(uint4*)&As[lrow + 64][seg * 8] = aR1;
        *(uint4*)&Bs[lrow][seg * 8]      = bR0;
        *(uint4*)&Bs[lrow + 64][seg * 8] = bR1;
        __syncthreads();

        int kn = k0 + BKH;
        if (kn < K) {   // prefetch next chunk (hidden under MMA)
            aR0 = *(const uint4*)(gA1 + kn);
            aR1 = *(const uint4*)(gA2 + kn);
            bR0 = *(const uint4*)(gB1 + kn);
            bR1 = *(const uint4*)(gB2 + kn);
        }

#pragma unroll
        for (int kk = 0; kk < 2; ++kk) {
            const int kb = kk * 16;
            uint32_t a[4][4], b[4][2];
#pragma unroll
            for (int mt = 0; mt < 4; ++mt) {
                int row = wm * 64 + mt * 16 + grp;
                a[mt][0] = *(const uint32_t*)&As[row][kb + qid * 2];
                a[mt][1] = *(const uint32_t*)&As[row + 8][kb + qid * 2];
                a[mt][2] = *(const uint32_t*)&As[row][kb + qid * 2 + 8];
                a[mt][3] = *(const uint32_t*)&As[row + 8][kb + qid * 2 + 8];
            }
#pragma unroll
            for (int nt = 0; nt < 4; ++nt) {
                int n = wn * 32 + nt * 8 + grp;
                b[nt][0] = *(const uint32_t*)&Bs[n][kb + qid * 2];
                b[nt][1] = *(const uint32_t*)&Bs[n][kb + qid * 2 + 8];
            }
#pragma unroll
            for (int mt = 0; mt < 4; ++mt)
#pragma unroll
                for (int nt = 0; nt < 4; ++nt)
                    mma_f16(c[mt][nt], a[mt], b[nt]);
        }
    }

    // epilogue (m16n8 fp32 accumulator: c0,c1 row grp; c2,c3 row grp+8)
#pragma unroll
    for (int mt = 0; mt < 4; ++mt) {
#pragma unroll
        for (int nt = 0; nt < 4; ++nt) {
            int row = mBlk + wm * 64 + mt * 16 + grp;
            int col = nBlk + wn * 32 + nt * 8 + qid * 2;
            *(float2*)&C[(size_t)row * N + col] =
                make_float2(c[mt][nt][0], c[mt][nt][1]);
            *(float2*)&C[(size_t)(row + 8) * N + col] =
                make_float2(c[mt][nt][2], c[mt][nt][3]);
        }
    }
}

// ---- elementwise -------------------------------------------------------------
__device__ __forceinline__ float sigmoidf_(float x) {
    return 1.0f / (1.0f + __expf(-x));
}

__global__ void e1_kernel(const float* __restrict__ h_re,
                          const float* __restrict__ h_im)
{
    int idx = blockIdx.x * blockDim.x + threadIdx.x;
    int b = idx >> 8, j = idx & 255;
    size_t row = (size_t)b * G1_N;
    float rr = sigmoidf_(g_C1[row + j]       + g_bias[j]);
    float ri = sigmoidf_(g_C1[row + 256 + j] + g_bias[256 + j]);
    float hr = h_re[idx], hi = h_im[idx];
    size_t r2 = (size_t)b * 512;
    g_RHh[r2 + j]       = __float2half(rr * hr - ri * hi);
    g_RHh[r2 + 256 + j] = __float2half(rr * hi + ri * hr);
}

__global__ void e2_kernel(const float* __restrict__ h_re,
                          const float* __restrict__ h_im,
                          float* __restrict__ out)
{
    int idx = blockIdx.x * blockDim.x + threadIdx.x;
    int b = idx >> 8, j = idx & 255;
    size_t r1 = (size_t)b * G1_N;
    size_t r2 = (size_t)b * 512;
    float zr = sigmoidf_(g_C1[r1 + 512 + j] + g_bias[512 + j]);
    float zi = sigmoidf_(g_C1[r1 + 768 + j] + g_bias[768 + j]);
    float er = g_C2[r2 + j]       + g_C1[r1 + 1024 + j] + g_bias[1024 + j];
    float ei = g_C2[r2 + 256 + j] + g_C1[r1 + 1280 + j] + g_bias[1280 + j];
    float hhr = tanhf(er);
    float hhi = tanhf(ei);
    float hr = h_re[idx], hi = h_im[idx];
    out[idx] = (1.0f - zr) * hr + zi * hi + zr * hhr - zi * hhi;
    out[(size_t)B_ROWS * HDIM + idx] =
        (1.0f - zr) * hi - zi * hr + zr * hhi + zi * hhr;
}

// ---- launch -------------------------------------------------------------------
extern "C" void kernel_launch(void* const* d_in, const int* in_sizes, int n_in,
                              void* d_out, int out_size)
{
    const float* x_re    = (const float*)d_in[0];
    const float* x_im    = (const float*)d_in[1];
    const float* h_re    = (const float*)d_in[2];
    const float* h_im    = (const float*)d_in[3];
    const float* wr_w_re = (const float*)d_in[4];
    const float* wr_w_im = (const float*)d_in[5];
    const float* wr_b_re = (const float*)d_in[6];
    const float* wr_b_im = (const float*)d_in[7];
    const float* wz_w_re = (const float*)d_in[8];
    const float* wz_w_im = (const float*)d_in[9];
    const float* wz_b_re = (const float*)d_in[10];
    const float* wz_b_im = (const float*)d_in[11];
    const float* wh_w_re = (const float*)d_in[12];
    const float* wh_w_im = (const float*)d_in[13];
    const float* wh_b_re = (const float*)d_in[14];
    const float* wh_b_im = (const float*)d_in[15];
    const float* ur_w_re = (const float*)d_in[16];
    const float* ur_w_im = (const float*)d_in[17];
    const float* uz_w_re = (const float*)d_in[18];
    const float* uz_w_im = (const float*)d_in[19];
    const float* uh_w_re = (const float*)d_in[20];
    const float* uh_w_im = (const float*)d_in[21];

    prep_g1<<<(G1_N * G1_K) / 256, 256>>>(wr_w_re, wr_w_im, wz_w_re, wz_w_im,
                                          wh_w_re, wh_w_im, ur_w_re, ur_w_im,
                                          uz_w_re, uz_w_im, uh_w_re, uh_w_im);
    prep_g2<<<(G2_N * G2_K) / 256, 256>>>(wh_w_re, wh_w_im);
    prep_bias<<<G1_N / 256, 256>>>(wr_b_re, wr_b_im, wz_b_re, wz_b_im,
                                   wh_b_re, wh_b_im);
    convA<<<(B_ROWS * 256) / 256, 256>>>(x_re, x_im, h_re, h_im);

    dim3 blk(256);
    dim3 grid1(G1_N / BN, B_ROWS / BM);   // 12 x 128
    hgemm<<<grid1, blk>>>(0);

    e1_kernel<<<(B_ROWS * HDIM) / 256, 256>>>(h_re, h_im);

    dim3 grid2(G2_N / BN, B_ROWS / BM);   // 4 x 128
    hgemm<<<grid2, blk>>>(1);

    e2_kernel<<<(B_ROWS * HDIM) / 256, 256>>>(h_re, h_im, (float*)d_out);
}

// round 7
// speedup vs baseline: 4.7842x; 1.1573x over previous
#include <cuda_runtime.h>
#include <cuda_fp16.h>
#include <cstdint>

// ---------------------------------------------------------------------------
// complexGRUCell: B=16384, I=256, H=256, fp32 in/out.
// fp16 tensor-core GEMMs (mma.m16n8k16.f32.f16.f16.f32) with ldmatrix
// fragment loads and a 3-stage cp.async smem pipeline.
// All __device__ globals resolved INSIDE device code via mode flags
// (host-side __device__-symbol args silently alias the host shadow on
// GB300/ATS — root cause of R4/R5 failures).
// ---------------------------------------------------------------------------

#define B_ROWS 16384
#define HDIM   256
#define G1_N   1536
#define G1_K   1024
#define G2_N   512
#define G2_K   512

__device__ __half g_G1h[G1_N * G1_K];
__device__ __half g_G2h[G2_N * G2_K];
__device__ __half g_Ah[(size_t)B_ROWS * G1_K];
__device__ __half g_RHh[(size_t)B_ROWS * 512];
__device__ float  g_bias[G1_N];
__device__ float  g_C1[(size_t)B_ROWS * G1_N];
__device__ float  g_C2[(size_t)B_ROWS * 512];

// ---- PTX helpers ------------------------------------------------------------
__device__ __forceinline__ uint32_t smem_u32(const void* p) {
    uint32_t a;
    asm("{ .reg .u64 t; cvta.to.shared.u64 t, %1; cvt.u32.u64 %0, t; }"
        : "=r"(a) : "l"(p));
    return a;
}
__device__ __forceinline__ void cp16(uint32_t s, const void* g) {
    asm volatile("cp.async.cg.shared.global [%0], [%1], 16;" :: "r"(s), "l"(g));
}
__device__ __forceinline__ void cp_commit() {
    asm volatile("cp.async.commit_group;" ::: "memory");
}
__device__ __forceinline__ void cp_wait1() {
    asm volatile("cp.async.wait_group 1;" ::: "memory");
}
__device__ __forceinline__ void cp_wait0() {
    asm volatile("cp.async.wait_group 0;" ::: "memory");
}
__device__ __forceinline__ void ldsm4(uint32_t* r, uint32_t addr) {
    asm volatile("ldmatrix.sync.aligned.m8n8.x4.shared.b16 {%0,%1,%2,%3}, [%4];"
                 : "=r"(r[0]), "=r"(r[1]), "=r"(r[2]), "=r"(r[3]) : "r"(addr));
}
__device__ __forceinline__ void mma_f16(float* c, const uint32_t* a,
                                        const uint32_t* b) {
    asm volatile(
        "mma.sync.aligned.m16n8k16.row.col.f32.f16.f16.f32 "
        "{%0,%1,%2,%3}, {%4,%5,%6,%7}, {%8,%9}, {%0,%1,%2,%3};"
        : "+f"(c[0]), "+f"(c[1]), "+f"(c[2]), "+f"(c[3])
        : "r"(a[0]), "r"(a[1]), "r"(a[2]), "r"(a[3]), "r"(b[0]), "r"(b[1]));
}

// ---- weight / activation preparation ----------------------------------------
__global__ void prep_g1(const float* __restrict__ wr_re, const float* __restrict__ wr_im,
                        const float* __restrict__ wz_re, const float* __restrict__ wz_im,
                        const float* __restrict__ wh_re, const float* __restrict__ wh_im,
                        const float* __restrict__ ur_re, const float* __restrict__ ur_im,
                        const float* __restrict__ uz_re, const float* __restrict__ uz_im,
                        const float* __restrict__ uh_re, const float* __restrict__ uh_im)
{
    int idx = blockIdx.x * blockDim.x + threadIdx.x;
    int n = idx >> 10, k = idx & 1023;
    int g = n >> 8,  j = n & 255;
    int kg = k >> 8, kc = k & 255;

    const float *Wre, *Wim, *Ure, *Uim;
    if (g < 2)      { Wre = wr_re; Wim = wr_im; Ure = ur_re; Uim = ur_im; }
    else if (g < 4) { Wre = wz_re; Wim = wz_im; Ure = uz_re; Uim = uz_im; }
    else            { Wre = wh_re; Wim = wh_im; Ure = uh_re; Uim = uh_im; }
    bool isIm = (g & 1) != 0;
    bool isH  = (g >= 4);

    int wj = j * 512;
    int uj = j * 256;
    float v;
    if (kg == 0) {
        v = isIm ?  Wim[wj + kc] : Wre[wj + kc];
    } else if (kg == 1) {
        v = isIm ?  Wre[wj + kc] : -Wim[wj + kc];
    } else if (kg == 2) {
        if (isIm) v = (isH ? 0.f : Wim[wj + 256 + kc]) + Uim[uj + kc];
        else      v = (isH ? 0.f : Wre[wj + 256 + kc]) + Ure[uj + kc];
    } else {
        if (isIm) v =  (isH ? 0.f : Wre[wj + 256 + kc]) + Ure[uj + kc];
        else      v = -((isH ? 0.f : Wim[wj + 256 + kc]) + Uim[uj + kc]);
    }
    g_G1h[idx] = __float2half(v);
}

__global__ void prep_g2(const float* __restrict__ wh_re,
                        const float* __restrict__ wh_im)
{
    int idx = blockIdx.x * blockDim.x + threadIdx.x;
    int n = idx >> 9, k = idx & 511;
    int g = n >> 8,  j = n & 255;
    int kg = k >> 8, kc = k & 255;
    float wre = wh_re[j * 512 + 256 + kc];
    float wim = wh_im[j * 512 + 256 + kc];
    float v = (g == 0) ? ((kg == 0) ? wre : -wim)
                       : ((kg == 0) ? wim :  wre);
    g_G2h[idx] = __float2half(v);
}

__global__ void prep_bias(const float* __restrict__ wr_b_re, const float* __restrict__ wr_b_im,
                          const float* __restrict__ wz_b_re, const float* __restrict__ wz_b_im,
                          const float* __restrict__ wh_b_re, const float* __restrict__ wh_b_im)
{
    int idx = blockIdx.x * blockDim.x + threadIdx.x;
    int g = idx >> 8, j = idx & 255;
    const float *br, *bi;
    if (g < 2)      { br = wr_b_re; bi = wr_b_im; }
    else if (g < 4) { br = wz_b_re; bi = wz_b_im; }
    else            { br = wh_b_re; bi = wh_b_im; }
    g_bias[idx] = (g & 1) ? (br[j] + bi[j]) : (br[j] - bi[j]);
}

__global__ void convA(const float* __restrict__ x_re, const float* __restrict__ x_im,
                      const float* __restrict__ h_re, const float* __restrict__ h_im)
{
    int idx = blockIdx.x * blockDim.x + threadIdx.x;   // < B*256
    int b = idx >> 8;
    int k = (idx & 255) << 2;
    int plane = k >> 8, kc = k & 255;
    const float* src = (plane == 0) ? x_re : (plane == 1) ? x_im
                     : (plane == 2) ? h_re : h_im;
    float4 v = *(const float4*)(src + (size_t)b * 256 + kc);
    __half2* dst = (__half2*)(g_Ah + (size_t)b * 1024 + k);
    dst[0] = __floats2half2_rn(v.x, v.y);
    dst[1] = __floats2half2_rn(v.z, v.w);
}

// ---- fp16 tensor-core GEMM: C[M,N] = A[M,K] @ W[N,K]^T ----------------------
// CTA 128x128, BK=32 halves, 3 cp.async stages, 8 warps (2m x 4n), m16n8k16,
// ldmatrix.x4 fragment loads.
#define BM 128
#define BN 128
#define BKH 32
#define ROWB 80                       // bytes per smem row (64 + 16 pad)
#define A_ST (BM * ROWB)              // 10240
#define STAGE_B (2 * A_ST)            // 20480
#define STAGES 3
#define HG_SMEM (STAGES * STAGE_B)    // 61440

__global__ void __launch_bounds__(256, 2)
hgemm(int mode)
{
    extern __shared__ char smem[];
    const uint32_t sb = smem_u32(smem);

    const __half* A;
    const __half* W;
    float* C;
    int lda, N, K;
    if (mode == 0) {
        A = g_Ah;  W = g_G1h; C = g_C1; lda = G1_K; N = G1_N; K = G1_K;
    } else {
        A = g_RHh; W = g_G2h; C = g_C2; lda = G2_K; N = G2_N; K = G2_K;
    }

    const int tid  = threadIdx.x;
    const int lane = tid & 31;
    const int wid  = tid >> 5;
    const int wm   = wid & 1;
    const int wn   = wid >> 1;
    const int mBlk = blockIdx.y * BM;
    const int nBlk = blockIdx.x * BN;
    const int NK   = K / BKH;

    // loader: 256 threads x (2 A-rows + 2 B-rows), 16B each
    const int lrow = tid >> 2;         // 0..63
    const int seg  = tid & 3;
    const __half* gA1 = A + (size_t)(mBlk + lrow)      * lda + seg * 8;
    const __half* gA2 = A + (size_t)(mBlk + lrow + 64) * lda + seg * 8;
    const __half* gB1 = W + (size_t)(nBlk + lrow)      * K   + seg * 8;
    const __half* gB2 = W + (size_t)(nBlk + lrow + 64) * K   + seg * 8;
    const uint32_t sA1 = sb + lrow * ROWB + seg * 16;
    const uint32_t sA2 = sA1 + 64 * ROWB;
    const uint32_t sB1 = sA1 + A_ST;
    const uint32_t sB2 = sB1 + 64 * ROWB;

    // ldmatrix lane offsets (verified against PTX m16n8k16 fragment layout)
    const int aRow = lane & 15;
    const int aK   = (lane >> 4) << 3;
    uint32_t aOff[4];
#pragma unroll
    for (int mt = 0; mt < 4; ++mt)
        aOff[mt] = (uint32_t)((wm * 64 + mt * 16 + aRow) * ROWB + aK * 2);
    const int bRow = ((lane >> 4) << 3) + (lane & 7);
    const int bK   = lane & 8;
    uint32_t bOff[2];
#pragma unroll
    for (int p = 0; p < 2; ++p)
        bOff[p] = (uint32_t)(A_ST + (wn * 32 + p * 16 + bRow) * ROWB + bK * 2);

    float c[4][4][4];
#pragma unroll
    for (int i = 0; i < 4; ++i)
#pragma unroll
        for (int j = 0; j < 4; ++j)
#pragma unroll
            for (int r = 0; r < 4; ++r) c[i][j][r] = 0.f;

    auto load = [&](int st, int k) {
        uint32_t off = (uint32_t)(st * STAGE_B);
        int kh = k * BKH;
        cp16(sA1 + off, gA1 + kh);
        cp16(sA2 + off, gA2 + kh);
        cp16(sB1 + off, gB1 + kh);
        cp16(sB2 + off, gB2 + kh);
    };

    load(0, 0); cp_commit();
    load(1, 1); cp_commit();

    for (int k = 0; k < NK; ++k) {
        if (k < NK - 1) cp_wait1(); else cp_wait0();
        __syncthreads();
        if (k + 2 < NK) {
            load((k + 2) % STAGES, k + 2);
            cp_commit();
        }

        const uint32_t base = (uint32_t)((k % STAGES) * STAGE_B);
#pragma unroll
        for (int kk = 0; kk < 2; ++kk) {
            const uint32_t koff = kk * 32;   // 16 halves = 32 bytes
            uint32_t a[4][4], b[2][4];
#pragma unroll
            for (int mt = 0; mt < 4; ++mt)
                ldsm4(a[mt], sb + base + aOff[mt] + koff);
#pragma unroll
            for (int p = 0; p < 2; ++p)
                ldsm4(b[p], sb + base + bOff[p] + koff);
#pragma unroll
            for (int mt = 0; mt < 4; ++mt)
#pragma unroll
                for (int nt = 0; nt < 4; ++nt)
                    mma_f16(c[mt][nt], a[mt], &b[nt >> 1][(nt & 1) * 2]);
        }
    }

    // epilogue
    const int grp = lane >> 2;
    const int qid = lane & 3;
#pragma unroll
    for (int mt = 0; mt < 4; ++mt) {
#pragma unroll
        for (int nt = 0; nt < 4; ++nt) {
            int row = mBlk + wm * 64 + mt * 16 + grp;
            int col = nBlk + wn * 32 + nt * 8 + qid * 2;
            *(float2*)&C[(size_t)row * N + col] =
                make_float2(c[mt][nt][0], c[mt][nt][1]);
            *(float2*)&C[(size_t)(row + 8) * N + col] =
                make_float2(c[mt][nt][2], c[mt][nt][3]);
        }
    }
}

// ---- elementwise -------------------------------------------------------------
__device__ __forceinline__ float sigmoidf_(float x) {
    return 1.0f / (1.0f + __expf(-x));
}

__global__ void e1_kernel(const float* __restrict__ h_re,
                          const float* __restrict__ h_im)
{
    int idx = blockIdx.x * blockDim.x + threadIdx.x;
    int b = idx >> 8, j = idx & 255;
    size_t row = (size_t)b * G1_N;
    float rr = sigmoidf_(g_C1[row + j]       + g_bias[j]);
    float ri = sigmoidf_(g_C1[row + 256 + j] + g_bias[256 + j]);
    float hr = h_re[idx], hi = h_im[idx];
    size_t r2 = (size_t)b * 512;
    g_RHh[r2 + j]       = __float2half(rr * hr - ri * hi);
    g_RHh[r2 + 256 + j] = __float2half(rr * hi + ri * hr);
}

__global__ void e2_kernel(const float* __restrict__ h_re,
                          const float* __restrict__ h_im,
                          float* __restrict__ out)
{
    int idx = blockIdx.x * blockDim.x + threadIdx.x;
    int b = idx >> 8, j = idx & 255;
    size_t r1 = (size_t)b * G1_N;
    size_t r2 = (size_t)b * 512;
    float zr = sigmoidf_(g_C1[r1 + 512 + j] + g_bias[512 + j]);
    float zi = sigmoidf_(g_C1[r1 + 768 + j] + g_bias[768 + j]);
    float er = g_C2[r2 + j]       + g_C1[r1 + 1024 + j] + g_bias[1024 + j];
    float ei = g_C2[r2 + 256 + j] + g_C1[r1 + 1280 + j] + g_bias[1280 + j];
    float hhr = tanhf(er);
    float hhi = tanhf(ei);
    float hr = h_re[idx], hi = h_im[idx];
    out[idx] = (1.0f - zr) * hr + zi * hi + zr * hhr - zi * hhi;
    out[(size_t)B_ROWS * HDIM + idx] =
        (1.0f - zr) * hi - zi * hr + zr * hhi + zi * hhr;
}

// ---- launch -------------------------------------------------------------------
extern "C" void kernel_launch(void* const* d_in, const int* in_sizes, int n_in,
                              void* d_out, int out_size)
{
    const float* x_re    = (const float*)d_in[0];
    const float* x_im    = (const float*)d_in[1];
    const float* h_re    = (const float*)d_in[2];
    const float* h_im    = (const float*)d_in[3];
    const float* wr_w_re = (const float*)d_in[4];
    const float* wr_w_im = (const float*)d_in[5];
    const float* wr_b_re = (const float*)d_in[6];
    const float* wr_b_im = (const float*)d_in[7];
    const float* wz_w_re = (const float*)d_in[8];
    const float* wz_w_im = (const float*)d_in[9];
    const float* wz_b_re = (const float*)d_in[10];
    const float* wz_b_im = (const float*)d_in[11];
    const float* wh_w_re = (const float*)d_in[12];
    const float* wh_w_im = (const float*)d_in[13];
    const float* wh_b_re = (const float*)d_in[14];
    const float* wh_b_im = (const float*)d_in[15];
    const float* ur_w_re = (const float*)d_in[16];
    const float* ur_w_im = (const float*)d_in[17];
    const float* uz_w_re = (const float*)d_in[18];
    const float* uz_w_im = (const float*)d_in[19];
    const float* uh_w_re = (const float*)d_in[20];
    const float* uh_w_im = (const float*)d_in[21];

    static int smem_set = 0;
    if (!smem_set) {
        cudaFuncSetAttribute(hgemm, cudaFuncAttributeMaxDynamicSharedMemorySize,
                             HG_SMEM);
        smem_set = 1;
    }

    prep_g1<<<(G1_N * G1_K) / 256, 256>>>(wr_w_re, wr_w_im, wz_w_re, wz_w_im,
                                          wh_w_re, wh_w_im, ur_w_re, ur_w_im,
                                          uz_w_re, uz_w_im, uh_w_re, uh_w_im);
    prep_g2<<<(G2_N * G2_K) / 256, 256>>>(wh_w_re, wh_w_im);
    prep_bias<<<G1_N / 256, 256>>>(wr_b_re, wr_b_im, wz_b_re, wz_b_im,
                                   wh_b_re, wh_b_im);
    convA<<<(B_ROWS * 256) / 256, 256>>>(x_re, x_im, h_re, h_im);

    dim3 blk(256);
    dim3 grid1(G1_N / BN, B_ROWS / BM);   // 12 x 128
    hgemm<<<grid1, blk, HG_SMEM>>>(0);

    e1_kernel<<<(B_ROWS * HDIM) / 256, 256>>>(h_re, h_im);

    dim3 grid2(G2_N / BN, B_ROWS / BM);   // 4 x 128
    hgemm<<<grid2, blk, HG_SMEM>>>(1);

    e2_kernel<<<(B_ROWS * HDIM) / 256, 256>>>(h_re, h_im, (float*)d_out);
}